// round 15
// baseline (speedup 1.0000x reference)
#include <cuda_runtime.h>
#include <cuda_bf16.h>
#include <math.h>
#include <stdint.h>

// Problem dims (fixed)
#define BATCH   1024
#define DIN     256
#define DH      512
#define DH2     1024
#define DOUT    128
#define NLAYERS 5
#define NBLK    256
#define NTHR    256

// ============================================================================
// Fragment-order global layouts:
//  A plane (M x K):  [M/16][K/16][32 lanes][4 u32]  (u32 = bf16 pair (k,k+1))
//  B plane (N x K):  [N/8 ][K/16][32 lanes][2 u32]
// ============================================================================

__device__ __align__(16) uint32_t g_aP [2][BATCH * DH  / 2];
__device__ __align__(16) uint32_t g_z1P[2][BATCH * DH2 / 2];
__device__ __align__(16) uint32_t g_z2P[2][BATCH * DH2 / 2];
__device__ __align__(16) uint32_t g_W1P[2][NLAYERS][DH2 * DH  / 2];
__device__ __align__(16) uint32_t g_W2P[2][NLAYERS][DH2 * DH2 / 2];
__device__ __align__(16) uint32_t g_W3P[2][NLAYERS][DH  * DH2 / 2];
// MLP weight planes
__device__ __align__(16) uint32_t g_Wi1P[2][DIN * DH  / 2];
__device__ __align__(16) uint32_t g_WrP [2][DIN * DH  / 2];
__device__ __align__(16) uint32_t g_Wi2P[2][DH  * DH  / 2];
__device__ __align__(16) uint32_t g_Wo1P[2][DH  * DH  / 2];
__device__ __align__(16) uint32_t g_Wo2P[2][DH  * DOUT / 2];
__device__ __align__(16) uint32_t g_xP  [2][BATCH * DIN / 2];

__device__ float g_yA[BATCH * DH];
__device__ float g_yB[BATCH * DH];
__device__ float g_ks[BATCH * DH];     // k1 save for RK3

__device__ __forceinline__ uint32_t aIdx(int r, int c, int Ka) {
    return (uint32_t)(((r >> 4) * Ka + (c >> 4)) * 128
         + ((r & 7) * 4 + ((c >> 1) & 3)) * 4
         + (((r >> 3) & 1) | (((c >> 3) & 1) << 1)));
}
__device__ __forceinline__ uint32_t bIdx(int n, int k, int Ka) {
    return (uint32_t)(((n >> 3) * Ka + (k >> 4)) * 64
         + ((n & 7) * 4 + ((k >> 1) & 3)) * 2
         + ((k >> 3) & 1));
}

__device__ __forceinline__ void split2(float v, uint32_t& hi16, uint32_t& lo16) {
    __nv_bfloat16 h = __float2bfloat16(v);
    __nv_bfloat16 l = __float2bfloat16(v - __bfloat162float(h));
    hi16 = (uint32_t)__bfloat16_as_ushort(h);
    lo16 = (uint32_t)__bfloat16_as_ushort(l);
}

__device__ __forceinline__ float tanh_fast(float x) {
    float e = __expf(fminf(2.0f * x, 80.0f));
    return __fdividef(e - 1.0f, e + 1.0f);
}

// ============================ MMA + cp.async =================================
__device__ __forceinline__ void mma16816(float c[4], const uint32_t a[4],
                                         const uint32_t b[2]) {
    asm volatile(
        "mma.sync.aligned.m16n8k16.row.col.f32.bf16.bf16.f32 "
        "{%0,%1,%2,%3}, {%4,%5,%6,%7}, {%8,%9}, {%0,%1,%2,%3};"
        : "+f"(c[0]), "+f"(c[1]), "+f"(c[2]), "+f"(c[3])
        : "r"(a[0]), "r"(a[1]), "r"(a[2]), "r"(a[3]), "r"(b[0]), "r"(b[1]));
}

__device__ __forceinline__ void cp16(void* smp, const void* g) {
    uint32_t s = (uint32_t)__cvta_generic_to_shared(smp);
    asm volatile("cp.async.cg.shared.global [%0], [%1], 16;" :: "r"(s), "l"(g));
}
#define CP_COMMIT() asm volatile("cp.async.commit_group;" ::: "memory")
#define CP_WAIT1()  asm volatile("cp.async.wait_group 1;" ::: "memory")

// B stage slot: 4 k-atoms, 16KB = 1024 uint4:
//   [katom(4)][plane(2)][natom(8)][16 uint4]; 256 threads x 4 uint4.
__device__ __forceinline__ void stage_B4(uint4* stb,
    const uint4* BhU, const uint4* BlU, int Ka, int it, int na0)
{
#pragma unroll
    for (int half = 0; half < 4; half++) {
        const int e = threadIdx.x + half * 256;
        const int katom = e >> 8;
        const int p  = (e >> 7) & 1;
        const int ba = (e >> 4) & 7;
        const int q  = e & 15;
        const uint4* B = p ? BlU : BhU;
        cp16(&stb[e], B + ((size_t)(na0 + ba) * Ka + (4 * it + katom)) * 16 + q);
    }
}

// ==================== split barrier with B prefetch ==========================
// arrive -> prefetch next GEMM's first 2 B slots -> wait. Group = 32 CTAs.
__device__ unsigned g_cnt[8 * 32];
__device__ volatile unsigned g_gen[8 * 32];

__device__ __forceinline__ void psync_pf(int p, bool do_pre,
    const uint32_t* BhP, const uint32_t* BlP, int Ka, int na0, uint4* sm)
{
    __syncthreads();
    const int ix = p * 32;
    unsigned gen = 0; int rel = 0;
    if (threadIdx.x == 0) {
        __threadfence();
        gen = g_gen[ix];
        if (atomicAdd(&g_cnt[ix], 1u) == 31) {
            g_cnt[ix] = 0;
            __threadfence();
            g_gen[ix] = gen + 1;
            rel = 1;
        }
    }
    if (do_pre) {
        const uint4* BhU = (const uint4*)BhP;
        const uint4* BlU = (const uint4*)BlP;
        stage_B4(sm,        BhU, BlU, Ka, 0, na0); CP_COMMIT();
        stage_B4(sm + 1024, BhU, BlU, Ka, 1, na0); CP_COMMIT();
    }
    if (threadIdx.x == 0) {
        if (!rel) { while (g_gen[ix] == gen) { __nanosleep(16); } }
        __threadfence();
    }
    __syncthreads();
}

// ============================ pipelined GEMMs ================================
// 64x64 tile (wide GEMMs); 8 warps 2(M) x 4(N); warp tile 32x16: acc[2][2][4]
template<bool PRE>
__device__ __forceinline__ void gemmW(
    const uint32_t* __restrict__ AhP, const uint32_t* __restrict__ AlP,
    const uint32_t* __restrict__ BhP, const uint32_t* __restrict__ BlP,
    int Ka, int mt, int nt, uint4* sm, float acc[2][2][4])
{
    const int lane = threadIdx.x & 31, wid = threadIdx.x >> 5;
    const int wm = wid >> 2, wn = wid & 3;
    const int ma0 = mt * 4 + wm * 2, na0 = nt * 8;
    const uint4* BhU = (const uint4*)BhP; const uint4* BlU = (const uint4*)BlP;
    const int bpo = (wn * 2) * 32 + lane;   // warp smem offset (uint2)

    const uint4* pA0 = (const uint4*)AhP + (size_t)ma0 * Ka * 32 + lane;
    const uint4* pA1 = pA0 + (size_t)Ka * 32;
    const uint4* pA2 = (const uint4*)AlP + (size_t)ma0 * Ka * 32 + lane;
    const uint4* pA3 = pA2 + (size_t)Ka * 32;

#pragma unroll
    for (int i = 0; i < 2; i++)
#pragma unroll
        for (int j = 0; j < 2; j++)
#pragma unroll
            for (int q = 0; q < 4; q++) acc[i][j][q] = 0.0f;

    uint4 Ab[2][4];
    Ab[0][0] = pA0[0];  Ab[0][1] = pA1[0];  Ab[0][2] = pA2[0];  Ab[0][3] = pA3[0];
    Ab[1][0] = pA0[32]; Ab[1][1] = pA1[32]; Ab[1][2] = pA2[32]; Ab[1][3] = pA3[32];

    const int NI = Ka >> 2;
    if (!PRE) {
        stage_B4(sm, BhU, BlU, Ka, 0, na0); CP_COMMIT();
        stage_B4(sm + 1024, BhU, BlU, Ka, 1, na0); CP_COMMIT();
    }

    int sc = 0, sp = 2;
#pragma unroll 1
    for (int it = 0; it < NI; it++) {
        CP_WAIT1();
        __syncthreads();
        if (it + 2 < NI)
            stage_B4(sm + sp * 1024, BhU, BlU, Ka, it + 2, na0);
        CP_COMMIT();
        const uint4* slot = sm + sc * 1024;

#pragma unroll
        for (int ka = 0; ka < 4; ka++) {
            const int k = 4 * it + ka;
            const int s = ka & 1;
            const uint2* bp = (const uint2*)(slot + ka * 256);
            uint2 Bh[2], Bl[2];
#pragma unroll
            for (int j = 0; j < 2; j++) {
                Bh[j] = bp[bpo + j * 32];
                Bl[j] = bp[256 + bpo + j * 32];
            }
            uint32_t ah[2][4] = {{Ab[s][0].x, Ab[s][0].y, Ab[s][0].z, Ab[s][0].w},
                                 {Ab[s][1].x, Ab[s][1].y, Ab[s][1].z, Ab[s][1].w}};
            uint32_t al[2][4] = {{Ab[s][2].x, Ab[s][2].y, Ab[s][2].z, Ab[s][2].w},
                                 {Ab[s][3].x, Ab[s][3].y, Ab[s][3].z, Ab[s][3].w}};
            if (k + 2 < Ka) {
                const size_t o = (size_t)(k + 2) * 32;
                Ab[s][0] = pA0[o]; Ab[s][1] = pA1[o];
                Ab[s][2] = pA2[o]; Ab[s][3] = pA3[o];
            }
            uint32_t bh[2][2] = {{Bh[0].x, Bh[0].y}, {Bh[1].x, Bh[1].y}};
            uint32_t bl[2][2] = {{Bl[0].x, Bl[0].y}, {Bl[1].x, Bl[1].y}};
#pragma unroll
            for (int i = 0; i < 2; i++)
#pragma unroll
                for (int j = 0; j < 2; j++) mma16816(acc[i][j], ah[i], bh[j]);
#pragma unroll
            for (int i = 0; i < 2; i++)
#pragma unroll
                for (int j = 0; j < 2; j++) mma16816(acc[i][j], al[i], bh[j]);
#pragma unroll
            for (int i = 0; i < 2; i++)
#pragma unroll
                for (int j = 0; j < 2; j++) mma16816(acc[i][j], ah[i], bl[j]);
        }
        sc = (sc == 2) ? 0 : sc + 1;
        sp = (sp == 2) ? 0 : sp + 1;
    }
}

// 32x64 tile (GEMM3/MLPs); 8 warps 2(M) x 4(N); warp tile 16x16: acc[2][4]
template<bool PRE>
__device__ __forceinline__ void gemm3(
    const uint32_t* __restrict__ AhP, const uint32_t* __restrict__ AlP,
    const uint32_t* __restrict__ BhP, const uint32_t* __restrict__ BlP,
    int Ka, int mt, int nt, uint4* sm, float acc[2][4])
{
    const int lane = threadIdx.x & 31, wid = threadIdx.x >> 5;
    const int wm = wid >> 2, wn = wid & 3;
    const int ma0 = mt * 2 + wm, na0 = nt * 8;
    const uint4* BhU = (const uint4*)BhP; const uint4* BlU = (const uint4*)BlP;
    const int bpo = (wn * 2) * 32 + lane;

    const uint4* pA0 = (const uint4*)AhP + (size_t)ma0 * Ka * 32 + lane;
    const uint4* pA2 = (const uint4*)AlP + (size_t)ma0 * Ka * 32 + lane;

#pragma unroll
    for (int j = 0; j < 2; j++)
#pragma unroll
        for (int q = 0; q < 4; q++) acc[j][q] = 0.0f;

    uint4 Ab[2][2];
    Ab[0][0] = pA0[0];  Ab[0][1] = pA2[0];
    Ab[1][0] = pA0[32]; Ab[1][1] = pA2[32];

    const int NI = Ka >> 2;
    if (!PRE) {
        stage_B4(sm, BhU, BlU, Ka, 0, na0); CP_COMMIT();
        stage_B4(sm + 1024, BhU, BlU, Ka, 1, na0); CP_COMMIT();
    }

    int sc = 0, sp = 2;
#pragma unroll 1
    for (int it = 0; it < NI; it++) {
        CP_WAIT1();
        __syncthreads();
        if (it + 2 < NI)
            stage_B4(sm + sp * 1024, BhU, BlU, Ka, it + 2, na0);
        CP_COMMIT();
        const uint4* slot = sm + sc * 1024;

#pragma unroll
        for (int ka = 0; ka < 4; ka++) {
            const int k = 4 * it + ka;
            const int s = ka & 1;
            const uint2* bp = (const uint2*)(slot + ka * 256);
            uint2 Bh[2], Bl[2];
#pragma unroll
            for (int j = 0; j < 2; j++) {
                Bh[j] = bp[bpo + j * 32];
                Bl[j] = bp[256 + bpo + j * 32];
            }
            uint32_t ah[4] = {Ab[s][0].x, Ab[s][0].y, Ab[s][0].z, Ab[s][0].w};
            uint32_t al[4] = {Ab[s][1].x, Ab[s][1].y, Ab[s][1].z, Ab[s][1].w};
            if (k + 2 < Ka) {
                const size_t o = (size_t)(k + 2) * 32;
                Ab[s][0] = pA0[o]; Ab[s][1] = pA2[o];
            }
            uint32_t bh[2][2] = {{Bh[0].x, Bh[0].y}, {Bh[1].x, Bh[1].y}};
            uint32_t bl[2][2] = {{Bl[0].x, Bl[0].y}, {Bl[1].x, Bl[1].y}};
#pragma unroll
            for (int j = 0; j < 2; j++) mma16816(acc[j], ah, bh[j]);
#pragma unroll
            for (int j = 0; j < 2; j++) mma16816(acc[j], al, bh[j]);
#pragma unroll
            for (int j = 0; j < 2; j++) mma16816(acc[j], ah, bl[j]);
        }
        sc = (sc == 2) ? 0 : sc + 1;
        sp = (sp == 2) ? 0 : sp + 1;
    }
}

// ============================ epilogues ======================================
// wide tile 64x64, warp tile 32x16
__device__ __forceinline__ void epi_tanhW(
    const float acc[2][2][4], const float* __restrict__ bias,
    int mt, int nt, uint32_t* __restrict__ Zh, uint32_t* __restrict__ Zl, int Kz)
{
    const int lane = threadIdx.x & 31;
    const int wid  = threadIdx.x >> 5;
    const int wm   = wid >> 2, wn = wid & 3;
#pragma unroll
    for (int i = 0; i < 2; i++) {
        const int rb = mt * 64 + wm * 32 + i * 16 + (lane >> 2);
#pragma unroll
        for (int j = 0; j < 2; j++) {
            const int c = nt * 64 + wn * 16 + j * 8 + (lane & 3) * 2;
            const float bc0 = bias[c], bc1 = bias[c + 1];
#pragma unroll
            for (int rh = 0; rh < 2; rh++) {
                const int r = rb + rh * 8;
                float v0 = tanh_fast(acc[i][j][rh * 2 + 0] + bc0);
                float v1 = tanh_fast(acc[i][j][rh * 2 + 1] + bc1);
                uint32_t h0, l0, h1, l1;
                split2(v0, h0, l0);
                split2(v1, h1, l1);
                const uint32_t idx = aIdx(r, c, Kz);
                Zh[idx] = h0 | (h1 << 16);
                Zl[idx] = l0 | (l1 << 16);
            }
        }
    }
}

// 32x64 tile, warp tile 16x16
__device__ __forceinline__ void epi_tanh3(
    const float acc[2][4], const float* __restrict__ bias,
    int mt, int nt, uint32_t* __restrict__ Zh, uint32_t* __restrict__ Zl, int Kz)
{
    const int lane = threadIdx.x & 31;
    const int wid  = threadIdx.x >> 5;
    const int wm   = wid >> 2, wn = wid & 3;
    const int rb = mt * 32 + wm * 16 + (lane >> 2);
#pragma unroll
    for (int j = 0; j < 2; j++) {
        const int c = nt * 64 + wn * 16 + j * 8 + (lane & 3) * 2;
        const float bc0 = bias[c], bc1 = bias[c + 1];
#pragma unroll
        for (int rh = 0; rh < 2; rh++) {
            const int r = rb + rh * 8;
            float v0 = tanh_fast(acc[j][rh * 2 + 0] + bc0);
            float v1 = tanh_fast(acc[j][rh * 2 + 1] + bc1);
            uint32_t h0, l0, h1, l1;
            split2(v0, h0, l0);
            split2(v1, h1, l1);
            const uint32_t idx = aIdx(r, c, Kz);
            Zh[idx] = h0 | (h1 << 16);
            Zl[idx] = l0 | (l1 << 16);
        }
    }
}

__device__ __forceinline__ void epi_plain3(
    const float acc[2][4], const float* __restrict__ bias,
    int mt, int nt, float* __restrict__ C)
{
    const int lane = threadIdx.x & 31;
    const int wid  = threadIdx.x >> 5;
    const int wm   = wid >> 2, wn = wid & 3;
    const int rb = mt * 32 + wm * 16 + (lane >> 2);
#pragma unroll
    for (int j = 0; j < 2; j++) {
        const int c = nt * 64 + wn * 16 + j * 8 + (lane & 3) * 2;
        const float bc0 = bias[c], bc1 = bias[c + 1];
#pragma unroll
        for (int rh = 0; rh < 2; rh++) {
            const int r = rb + rh * 8;
            ((float2*)C)[((size_t)r * DH + c) >> 1] =
                make_float2(acc[j][rh * 2 + 0] + bc0, acc[j][rh * 2 + 1] + bc1);
        }
    }
}

__device__ __forceinline__ void epi_resid3(
    const float acc[2][4], const float* __restrict__ bias,
    int mt, int nt, const float* __restrict__ R, float* __restrict__ Y)
{
    const int lane = threadIdx.x & 31;
    const int wid  = threadIdx.x >> 5;
    const int wm   = wid >> 2, wn = wid & 3;
    const int rb = mt * 32 + wm * 16 + (lane >> 2);
#pragma unroll
    for (int j = 0; j < 2; j++) {
        const int c = nt * 64 + wn * 16 + j * 8 + (lane & 3) * 2;
        const float bc0 = bias[c], bc1 = bias[c + 1];
#pragma unroll
        for (int rh = 0; rh < 2; rh++) {
            const int r = rb + rh * 8;
            const size_t fidx = ((size_t)r * DH + c) >> 1;
            float2 rv = ((const float2*)R)[fidx];
            float v0 = tanh_fast(acc[j][rh * 2 + 0] + bc0) + rv.x;
            float v1 = tanh_fast(acc[j][rh * 2 + 1] + bc1) + rv.y;
            ((float2*)Y)[fidx] = make_float2(v0, v1);
            uint32_t h0, l0, h1, l1;
            split2(v0, h0, l0);
            split2(v1, h1, l1);
            const uint32_t idx = aIdx(r, c, DH / 16);
            g_aP[0][idx] = h0 | (h1 << 16);
            g_aP[1][idx] = l0 | (l1 << 16);
        }
    }
}

// RK3 (Kutta) epilogue, h = 1:
//  st0: ks=k; yn = y + k/6;   a = y + 0.5 k
//  st1: yn += (2/3) k;        a = y + 2k - ks
//  st2: yn += k/6;            a = yn
__device__ __forceinline__ void epi_rk3(
    const float acc[2][4], const float* __restrict__ b3,
    int mt, int nt, const float* __restrict__ y, float* __restrict__ yn, int st)
{
    const int lane = threadIdx.x & 31;
    const int wid  = threadIdx.x >> 5;
    const int wm   = wid >> 2, wn = wid & 3;
    const int rb = mt * 32 + wm * 16 + (lane >> 2);
    const float wgt = (st == 1) ? (2.0f / 3.0f) : (1.0f / 6.0f);
#pragma unroll
    for (int j = 0; j < 2; j++) {
        const int c = nt * 64 + wn * 16 + j * 8 + (lane & 3) * 2;
        const float bc0 = b3[c], bc1 = b3[c + 1];
#pragma unroll
        for (int rh = 0; rh < 2; rh++) {
            const int r = rb + rh * 8;
            const size_t fidx = ((size_t)r * DH + c) >> 1;
            float k0 = acc[j][rh * 2 + 0] + bc0;
            float k1 = acc[j][rh * 2 + 1] + bc1;
            float2 yv   = ((const float2*)y)[fidx];
            float2 base = (st == 0) ? yv : ((const float2*)yn)[fidx];
            float yn0 = fmaf(wgt, k0, base.x);
            float yn1 = fmaf(wgt, k1, base.y);
            ((float2*)yn)[fidx] = make_float2(yn0, yn1);
            float a0, a1;
            if (st == 0) {
                ((float2*)g_ks)[fidx] = make_float2(k0, k1);
                a0 = fmaf(0.5f, k0, yv.x);
                a1 = fmaf(0.5f, k1, yv.y);
            } else if (st == 1) {
                float2 ks = ((const float2*)g_ks)[fidx];
                a0 = yv.x + 2.0f * k0 - ks.x;
                a1 = yv.y + 2.0f * k1 - ks.y;
            } else {
                a0 = yn0; a1 = yn1;
            }
            uint32_t h0, l0, h1, l1;
            split2(a0, h0, l0);
            split2(a1, h1, l1);
            const uint32_t idx = aIdx(r, c, DH / 16);
            g_aP[0][idx] = h0 | (h1 << 16);
            g_aP[1][idx] = l0 | (l1 << 16);
        }
    }
}

__device__ __forceinline__ void epi_out3(
    const float acc[2][4], const float* __restrict__ bias,
    int mt, int nt, float* __restrict__ out)
{
    const int lane = threadIdx.x & 31;
    const int wid  = threadIdx.x >> 5;
    const int wm   = wid >> 2, wn = wid & 3;
    const int rb = mt * 32 + wm * 16 + (lane >> 2);
#pragma unroll
    for (int j = 0; j < 2; j++) {
        const int c = nt * 64 + wn * 16 + j * 8 + (lane & 3) * 2;
        const float bc0 = bias[c], bc1 = bias[c + 1];
#pragma unroll
        for (int rh = 0; rh < 2; rh++) {
            const int r = rb + rh * 8;
            float v0 = tanh_fast(acc[j][rh * 2 + 0] + bc0);
            float v1 = tanh_fast(acc[j][rh * 2 + 1] + bc1);
            ((float2*)out)[((size_t)r * DOUT + c) >> 1] = make_float2(v0, v1);
        }
    }
}

// ============================ persistent kernel ==============================
__global__ __launch_bounds__(NTHR, 2)
void ode_mma(const float* __restrict__ bi1, const float* __restrict__ bi2,
             const float* __restrict__ br,
             const float* __restrict__ ob1, const float* __restrict__ ob2,
             const float* __restrict__ ob3,
             const float* __restrict__ bo1, const float* __restrict__ bo2,
             float* __restrict__ out)
{
    extern __shared__ uint4 smem[];
    const int b = blockIdx.x;
    const int panel = b >> 5;               // 8 panels of 128 batch rows
    const int sub   = b & 31;
    const int mtW = panel * 2 + (sub >> 4); // wide (N=1024): 64x64 tiles, 16x16
    const int ntW = sub & 15;
    const int mt3 = panel * 4 + (sub >> 3); // N<=512: 32x64 tiles, 32x8
    const int nt3 = sub & 7;

    float acc[2][2][4];
    float acc3[2][4];

    // ---------- input MLP ----------
    gemm3<false>(g_xP[0], g_xP[1], g_Wi1P[0], g_Wi1P[1], DIN / 16, mt3, nt3,
                 smem, acc3);
    epi_tanh3(acc3, bi1, mt3, nt3, g_z1P[0], g_z1P[1], DH / 16);
    gemm3<false>(g_xP[0], g_xP[1], g_WrP[0], g_WrP[1], DIN / 16, mt3, nt3,
                 smem, acc3);
    epi_plain3(acc3, br, mt3, nt3, g_yB);
    psync_pf(panel, true, g_Wi2P[0], g_Wi2P[1], DH / 16, nt3 * 8, smem);
    gemm3<true>(g_z1P[0], g_z1P[1], g_Wi2P[0], g_Wi2P[1], DH / 16, mt3, nt3,
                smem, acc3);
    epi_resid3(acc3, bi2, mt3, nt3, g_yB, g_yA);
    psync_pf(panel, true, g_W1P[0][0], g_W1P[1][0], DH / 16, ntW * 8, smem);

    // ---------- 5 ODE layers, RK3 (Kutta), h = 1 ----------
    float* y  = &g_yA[0];
    float* yn = &g_yB[0];

#pragma unroll 1
    for (int l = 0; l < NLAYERS; l++) {
        const uint32_t* B1h = g_W1P[0][l]; const uint32_t* B1l = g_W1P[1][l];
        const uint32_t* B2h = g_W2P[0][l]; const uint32_t* B2l = g_W2P[1][l];
        const uint32_t* B3h = g_W3P[0][l]; const uint32_t* B3l = g_W3P[1][l];
        const float* b1 = ob1 + l * DH2;
        const float* b2 = ob2 + l * DH2;
        const float* b3 = ob3 + l * DH;

#pragma unroll 1
        for (int st = 0; st < 3; st++) {
            // GEMM1's B preloaded by the previous psync_pf
            gemmW<true>(g_aP[0], g_aP[1], B1h, B1l, DH / 16, mtW, ntW,
                        smem, acc);
            epi_tanhW(acc, b1, mtW, ntW, g_z1P[0], g_z1P[1], DH2 / 16);
            psync_pf(panel, true, B2h, B2l, DH2 / 16, ntW * 8, smem);
            gemmW<true>(g_z1P[0], g_z1P[1], B2h, B2l, DH2 / 16, mtW, ntW,
                        smem, acc);
            epi_tanhW(acc, b2, mtW, ntW, g_z2P[0], g_z2P[1], DH2 / 16);
            psync_pf(panel, true, B3h, B3l, DH2 / 16, nt3 * 8, smem);
            gemm3<true>(g_z2P[0], g_z2P[1], B3h, B3l, DH2 / 16, mt3, nt3,
                        smem, acc3);
            epi_rk3(acc3, b3, mt3, nt3, y, yn, st);
            // prefetch next GEMM's B during the barrier
            const uint32_t *nBh, *nBl; int nna;
            if (st < 2)                { nBh = B1h;             nBl = B1l;
                                         nna = ntW * 8; }
            else if (l + 1 < NLAYERS)  { nBh = g_W1P[0][l + 1]; nBl = g_W1P[1][l + 1];
                                         nna = ntW * 8; }
            else                       { nBh = g_Wo1P[0];       nBl = g_Wo1P[1];
                                         nna = nt3 * 8; }
            psync_pf(panel, true, nBh, nBl, DH / 16, nna, smem);
        }
        float* t = y; y = yn; yn = t;
    }

    // ---------- output MLP (Wo1 preloaded by last psync_pf) ----------
    gemm3<true>(g_aP[0], g_aP[1], g_Wo1P[0], g_Wo1P[1], DH / 16, mt3, nt3,
                smem, acc3);
    epi_tanh3(acc3, bo1, mt3, nt3, g_z1P[0], g_z1P[1], DH / 16);
    psync_pf(panel, nt3 < DOUT / 64, g_Wo2P[0], g_Wo2P[1], DH / 16, nt3 * 8, smem);
    if (nt3 < DOUT / 64) {
        gemm3<true>(g_z1P[0], g_z1P[1], g_Wo2P[0], g_Wo2P[1], DH / 16, mt3, nt3,
                    smem, acc3);
        epi_out3(acc3, bo2, mt3, nt3, out);
    }
}

// ============================ prep kernel ====================================
#define S1 (DH * DH2)
#define S2 (DH2 * DH2)
#define S3 (DH2 * DH)
#define P1 (S1 / 2)
#define P2 (S2 / 2)
#define P3 (S3 / 2)
#define PL (P1 + P2 + P3)
#define E_I1 (DIN * DH / 2)
#define E_R  (DIN * DH / 2)
#define E_I2 (DH * DH / 2)
#define E_O1 (DH * DH / 2)
#define E_O2 (DH * DOUT / 2)
#define E_X  (BATCH * DIN / 2)
#define EXTRA (E_I1 + E_R + E_I2 + E_O1 + E_O2 + E_X)
#define TOTAL ((long long)NLAYERS * PL + EXTRA)

__global__ void prep_all(const float* __restrict__ W1,
                         const float* __restrict__ W2,
                         const float* __restrict__ W3,
                         const float* __restrict__ Wi1,
                         const float* __restrict__ Wr,
                         const float* __restrict__ Wi2,
                         const float* __restrict__ Wo1,
                         const float* __restrict__ Wo2,
                         const float* __restrict__ x)
{
    for (long long idx = blockIdx.x * (long long)blockDim.x + threadIdx.x;
         idx < TOTAL;
         idx += (long long)gridDim.x * blockDim.x) {
        if (idx < (long long)NLAYERS * PL) {
            const int l = (int)(idx / PL);
            int p = (int)(idx % PL);
            const float* W; int N, Ka; uint32_t *Ph, *Pl;
            if (p < P1)      { W = W1 + (size_t)l * S1; N = DH2; Ka = DH / 16;
                               Ph = g_W1P[0][l]; Pl = g_W1P[1][l]; }
            else if (p < P1 + P2) { p -= P1; W = W2 + (size_t)l * S2; N = DH2; Ka = DH2 / 16;
                               Ph = g_W2P[0][l]; Pl = g_W2P[1][l]; }
            else             { p -= P1 + P2; W = W3 + (size_t)l * S3; N = DH; Ka = DH2 / 16;
                               Ph = g_W3P[0][l]; Pl = g_W3P[1][l]; }
            const int kp = p / N, n = p % N, k = kp * 2;
            uint32_t h0, l0, h1, l1;
            split2(W[(size_t)k * N + n],       h0, l0);
            split2(W[(size_t)(k + 1) * N + n], h1, l1);
            const uint32_t o = bIdx(n, k, Ka);
            Ph[o] = h0 | (h1 << 16);
            Pl[o] = l0 | (l1 << 16);
        } else {
            long long q = idx - (long long)NLAYERS * PL;
            if (q < E_X) {
                const int p = (int)q;
                const int r = p / (DIN / 2);
                const int c = (p % (DIN / 2)) * 2;
                float2 v = ((const float2*)x)[p];
                uint32_t h0, l0, h1, l1;
                split2(v.x, h0, l0);
                split2(v.y, h1, l1);
                const uint32_t o = aIdx(r, c, DIN / 16);
                g_xP[0][o] = h0 | (h1 << 16);
                g_xP[1][o] = l0 | (l1 << 16);
            } else {
                q -= E_X;
                const float* W; int N, Ka; uint32_t *Ph, *Pl; int p;
                if (q < E_I1)            { p = (int)q; W = Wi1; N = DH; Ka = DIN / 16;
                                           Ph = g_Wi1P[0]; Pl = g_Wi1P[1]; }
                else if (q < E_I1 + E_R) { p = (int)(q - E_I1); W = Wr; N = DH; Ka = DIN / 16;
                                           Ph = g_WrP[0]; Pl = g_WrP[1]; }
                else if (q < E_I1 + E_R + E_I2) { p = (int)(q - E_I1 - E_R); W = Wi2; N = DH;
                                           Ka = DH / 16; Ph = g_Wi2P[0]; Pl = g_Wi2P[1]; }
                else if (q < E_I1 + E_R + E_I2 + E_O1) { p = (int)(q - E_I1 - E_R - E_I2);
                                           W = Wo1; N = DH; Ka = DH / 16;
                                           Ph = g_Wo1P[0]; Pl = g_Wo1P[1]; }
                else                     { p = (int)(q - E_I1 - E_R - E_I2 - E_O1);
                                           W = Wo2; N = DOUT; Ka = DH / 16;
                                           Ph = g_Wo2P[0]; Pl = g_Wo2P[1]; }
                const int kp = p / N, n = p % N, k = kp * 2;
                uint32_t h0, l0, h1, l1;
                split2(W[(size_t)k * N + n],       h0, l0);
                split2(W[(size_t)(k + 1) * N + n], h1, l1);
                const uint32_t o = bIdx(n, k, Ka);
                Ph[o] = h0 | (h1 << 16);
                Pl[o] = l0 | (l1 << 16);
            }
        }
    }
}

// ============================ host orchestration =============================
extern "C" void kernel_launch(void* const* d_in, const int* in_sizes, int n_in,
                              void* d_out, int out_size)
{
    (void)in_sizes; (void)n_in; (void)out_size;

    const float* x   = (const float*)d_in[0];
    const float* Wi1 = (const float*)d_in[1];
    const float* bi1 = (const float*)d_in[2];
    const float* Wi2 = (const float*)d_in[3];
    const float* bi2 = (const float*)d_in[4];
    const float* Wr  = (const float*)d_in[5];
    const float* br  = (const float*)d_in[6];
    const float* oW1 = (const float*)d_in[7];
    const float* ob1 = (const float*)d_in[8];
    const float* oW2 = (const float*)d_in[9];
    const float* ob2 = (const float*)d_in[10];
    const float* oW3 = (const float*)d_in[11];
    const float* ob3 = (const float*)d_in[12];
    const float* Wo1 = (const float*)d_in[13];
    const float* bo1 = (const float*)d_in[14];
    const float* Wo2 = (const float*)d_in[15];
    const float* bo2 = (const float*)d_in[16];

    static int smem_set = 0;
    const int SMEM_BYTES = 3 * 1024 * 16;   // 48KB per CTA (2 CTAs/SM)
    if (!smem_set) {
        cudaFuncSetAttribute(ode_mma, cudaFuncAttributeMaxDynamicSharedMemorySize,
                             SMEM_BYTES);
        smem_set = 1;
    }

    prep_all<<<1024, 256>>>(oW1, oW2, oW3, Wi1, Wr, Wi2, Wo1, Wo2, x);

    ode_mma<<<NBLK, NTHR, SMEM_BYTES>>>(bi1, bi2, br, ob1, ob2, ob3,
                                        bo1, bo2, (float*)d_out);
}